// round 13
// baseline (speedup 1.0000x reference)
#include <cuda_runtime.h>
#include <cstdint>
#include <math.h>

#define MAXN 100000
#define MAXE 1600000
#define D 64
#define EPSF 1e-12f
#define SEPS 1e-6f
#define TAUF 0.5f

// ---- scratch (device globals: no allocation allowed) ----
__device__ __align__(8)  float2 g_deghist[MAXN];   // {weighted deg, edge count}
__device__ __align__(16) float4 g_nodeacc[MAXN];   // {rowsum, cnt, ksum, pad}
__device__ float    g_rho[MAXN];
__device__ int      g_start[MAXN];     // CSR row start
__device__ int      g_cursor[MAXN];    // fill cursor / final end
__device__ int      g_row[MAXE];
__device__ int      g_col[MAXE];
__device__ float    g_kappa[MAXE];
__device__ float    g_whalf[MAXE];
__device__ __align__(8) float2 g_scw[MAXE];  // CSR payload {bitcast col, w_half}
__device__ __align__(16) float g_agg[MAXN * D];
__device__ unsigned g_maxbits;
__device__ int      g_base;
__device__ int      g_is64;

__device__ __forceinline__ int get_idx(const void* ei, long long pos) {
    if (g_is64) return (int)((const long long*)ei)[pos];
    return ((const int*)ei)[pos];
}

// ---- 0: zero node scratch + dtype detect (block 0) ----
__global__ void k_init(const int* __restrict__ eib, int n_nodes) {
    if (blockIdx.x == 0) {
        __shared__ int any;
        if (threadIdx.x == 0) any = 0;
        __syncthreads();
        int acc = 0;
        for (int j = threadIdx.x; j < 2048; j += blockDim.x)
            acc |= eib[2 * j + 1];
        if (acc != 0) atomicOr(&any, 1);
        __syncthreads();
        if (threadIdx.x == 0) {
            g_is64 = (any == 0) ? 1 : 0;
            g_maxbits = 0u;
            g_base = 0;
        }
    }
    int i = blockIdx.x * blockDim.x + threadIdx.x;
    if (i < n_nodes) {
        g_deghist[i] = make_float2(0.f, 0.f);
        g_nodeacc[i] = make_float4(0.f, 0.f, 0.f, 0.f);
    }
}

// ---- 1: convert + edge_index output + fused {deg,count} v2 reduction ----
__global__ void k_cvtdeg(const void* __restrict__ ei, const float* __restrict__ w,
                         float* __restrict__ out_ei, int n_edges) {
    int e = blockIdx.x * blockDim.x + threadIdx.x;
    if (e >= n_edges) return;
    int r = get_idx(ei, e);
    int c = get_idx(ei, (long long)n_edges + e);
    g_row[e] = r;
    g_col[e] = c;
    if (out_ei) {
        out_ei[e] = (float)r;
        out_ei[n_edges + e] = (float)c;
    }
    float* dst = (float*)&g_deghist[r];
    asm volatile("red.global.add.v2.f32 [%0], {%1,%2};"
                 :: "l"(dst), "f"(w[e]), "f"(1.0f) : "memory");
}

// ---- 2: kappa per edge (stored) + global max|kappa|; rider: CSR row starts ----
__global__ void k_kappa(int n_edges, int n_nodes) {
    __shared__ int sh[256];
    __shared__ int sbase;
    int t = threadIdx.x;

    if (blockIdx.x * 256u < (unsigned)n_nodes) {
        int n = blockIdx.x * 256 + t;
        int v = (n < n_nodes) ? (int)g_deghist[n].y : 0;
        sh[t] = v;
        __syncthreads();
        #pragma unroll
        for (int o = 1; o < 256; o <<= 1) {
            int u = (t >= o) ? sh[t - o] : 0;
            __syncthreads();
            sh[t] += u;
            __syncthreads();
        }
        int incl = sh[t];
        if (t == 255) sbase = atomicAdd(&g_base, incl);
        __syncthreads();
        if (n < n_nodes) {
            int s = sbase + incl - v;
            g_start[n] = s;
            g_cursor[n] = s;
        }
    }

    int e = blockIdx.x * blockDim.x + t;
    float m = 0.f;
    if (e < n_edges) {
        float idu = 2.f / fmaxf(g_deghist[g_row[e]].x, EPSF);
        float idv = 2.f / fmaxf(g_deghist[g_col[e]].x, EPSF);
        float kap = idu + idv - 2.f;
        g_kappa[e] = kap;
        m = fabsf(kap);
    }
    #pragma unroll
    for (int o = 16; o > 0; o >>= 1)
        m = fmaxf(m, __shfl_xor_sync(0xffffffffu, m, o));
    if ((t & 31) == 0)
        atomicMax(&g_maxbits, __float_as_uint(m));
}

// ---- 3: half-step + surgery + v4 node reduction + CSR payload scatter ----
__global__ void k_whalf(const float* __restrict__ w, int n_edges) {
    int e = blockIdx.x * blockDim.x + threadIdx.x;
    if (e >= n_edges) return;
    float dt = 0.5f / (__uint_as_float(g_maxbits) + 1e-6f);
    float kap = g_kappa[e];
    float wh = fmaxf(w[e] * (1.f - 0.5f * dt * kap), 0.f);
    bool mask = wh > SEPS;
    if (!mask) wh = 0.f;
    g_whalf[e] = wh;
    int r = g_row[e];
    float cntv = mask ? 1.f : 0.f;
    float kv   = mask ? kap : 0.f;
    float* dst = (float*)&g_nodeacc[r];
    asm volatile("red.global.add.v4.f32 [%0], {%1,%2,%3,%4};"
                 :: "l"(dst), "f"(wh), "f"(cntv), "f"(kv), "f"(0.f)
                 : "memory");
    if (mask) {
        int pos = atomicAdd(&g_cursor[r], 1);
        g_scw[pos] = make_float2(__int_as_float(g_col[e]), wh);
    }
}

// ---- 4: gather-accumulate (one warp/node, 4 edges in flight) + rho; rider: out_wn ----
__global__ void k_gather(const float* __restrict__ x,
                         float* __restrict__ out_wn,
                         int n_edges, int n_nodes) {
    // rider: out_wn[e] = whalf[e] / max(rowsum[row], eps), coalesced
    {
        int e = blockIdx.x * blockDim.x + threadIdx.x;
        if (e < n_edges && out_wn)
            out_wn[e] = g_whalf[e] / fmaxf(g_nodeacc[g_row[e]].x, EPSF);
    }

    int node = (blockIdx.x * blockDim.x + threadIdx.x) >> 5;
    if (node >= n_nodes) return;
    int lane = threadIdx.x & 31;
    int sub  = lane & 7;    // 8 lanes per edge, 2 float4 each = 256B row
    int grp  = lane >> 3;   // 0..3: 4 edges in flight
    int s = g_start[node];
    int epos = g_cursor[node];

    float4 a = g_nodeacc[node];
    float irs = 1.f / fmaxf(a.x, EPSF);
    if (lane == 0) {
        float mk = a.z / fmaxf(a.y, 1.f);
        g_rho[node] = 1.f / (1.f + expf(-mk));
    }

    float4 acc0 = make_float4(0.f, 0.f, 0.f, 0.f);
    float4 acc1 = make_float4(0.f, 0.f, 0.f, 0.f);
    #pragma unroll 2
    for (int p = s + grp; p < epos; p += 4) {
        float2 cw = g_scw[p];
        int   c  = __float_as_int(cw.x);
        float wh = cw.y;
        const float4* xr = (const float4*)(x + (size_t)c * D);
        float4 v0 = xr[sub];
        float4 v1 = xr[sub + 8];
        acc0.x += wh * v0.x; acc0.y += wh * v0.y;
        acc0.z += wh * v0.z; acc0.w += wh * v0.w;
        acc1.x += wh * v1.x; acc1.y += wh * v1.y;
        acc1.z += wh * v1.z; acc1.w += wh * v1.w;
    }
    #pragma unroll
    for (int o = 8; o <= 16; o <<= 1) {
        acc0.x += __shfl_xor_sync(0xffffffffu, acc0.x, o);
        acc0.y += __shfl_xor_sync(0xffffffffu, acc0.y, o);
        acc0.z += __shfl_xor_sync(0xffffffffu, acc0.z, o);
        acc0.w += __shfl_xor_sync(0xffffffffu, acc0.w, o);
        acc1.x += __shfl_xor_sync(0xffffffffu, acc1.x, o);
        acc1.y += __shfl_xor_sync(0xffffffffu, acc1.y, o);
        acc1.z += __shfl_xor_sync(0xffffffffu, acc1.z, o);
        acc1.w += __shfl_xor_sync(0xffffffffu, acc1.w, o);
    }
    if (grp == 0) {
        acc0.x *= irs; acc0.y *= irs; acc0.z *= irs; acc0.w *= irs;
        acc1.x *= irs; acc1.y *= irs; acc1.z *= irs; acc1.w *= irs;
        float* dst = g_agg + (size_t)node * D;
        ((float4*)dst)[sub]     = acc0;
        ((float4*)dst)[sub + 8] = acc1;
    }
}

// ---- FFMA2 helpers (packed f32x2, sm_103a) ----
__device__ __forceinline__ unsigned long long dup2(float v) {
    unsigned long long r;
    asm("mov.b64 %0, {%1, %1};" : "=l"(r) : "r"(__float_as_uint(v)));
    return r;
}
__device__ __forceinline__ void ffma2(unsigned long long& acc,
                                      unsigned long long a, unsigned long long b) {
    asm("fma.rn.f32x2 %0, %1, %2, %0;" : "+l"(acc) : "l"(a), "l"(b));
}
__device__ __forceinline__ void unpack2(unsigned long long v, float& lo, float& hi) {
    unsigned l, h;
    asm("mov.b64 {%0, %1}, %2;" : "=r"(l), "=r"(h) : "l"(v));
    lo = __uint_as_float(l); hi = __uint_as_float(h);
}

// ---- 5: fused dual GEMM (FFMA2): out = (rho*x)@Ws^T + agg@Wn^T + tau*x ----
#define TILE_N 128
__global__ __launch_bounds__(128, 2) void k_gemm(const float* __restrict__ x,
                                                 const float* __restrict__ Ws,
                                                 const float* __restrict__ Wn,
                                                 float* __restrict__ out,
                                                 int n_nodes) {
    extern __shared__ float smem[];
    float* sxT = smem;
    float* saT = sxT + D * TILE_N;
    float* swT = saT + D * TILE_N;
    float* snT = swT + D * D;

    int t = threadIdx.x;
    int nbase = blockIdx.x * TILE_N;

    for (int i = t; i < D * D; i += 128) {
        int k = i >> 6, d = i & 63;
        swT[k * D + d] = Ws[d * D + k];
        snT[k * D + d] = Wn[d * D + k];
    }
    for (int i = t; i < TILE_N * (D / 4); i += 128) {
        int n  = i & (TILE_N - 1);
        int k4 = i >> 7;
        int gn = nbase + n;
        float4 xv = make_float4(0.f, 0.f, 0.f, 0.f);
        float4 av = make_float4(0.f, 0.f, 0.f, 0.f);
        float rho = 0.f;
        if (gn < n_nodes) {
            xv  = *(const float4*)(x     + (size_t)gn * D + k4 * 4);
            av  = *(const float4*)(g_agg + (size_t)gn * D + k4 * 4);
            rho = g_rho[gn];
        }
        sxT[(k4 * 4 + 0) * TILE_N + n] = rho * xv.x;
        sxT[(k4 * 4 + 1) * TILE_N + n] = rho * xv.y;
        sxT[(k4 * 4 + 2) * TILE_N + n] = rho * xv.z;
        sxT[(k4 * 4 + 3) * TILE_N + n] = rho * xv.w;
        saT[(k4 * 4 + 0) * TILE_N + n] = av.x;
        saT[(k4 * 4 + 1) * TILE_N + n] = av.y;
        saT[(k4 * 4 + 2) * TILE_N + n] = av.z;
        saT[(k4 * 4 + 3) * TILE_N + n] = av.w;
    }
    __syncthreads();

    int ng = t >> 3;
    int dg = t & 7;

    unsigned long long acc[8][4];
    #pragma unroll
    for (int i = 0; i < 8; i++)
        #pragma unroll
        for (int j = 0; j < 4; j++) acc[i][j] = 0ull;

    #pragma unroll 2
    for (int k = 0; k < D; k++) {
        float4 a0 = *(float4*)&sxT[k * TILE_N + ng * 8];
        float4 a1 = *(float4*)&sxT[k * TILE_N + ng * 8 + 4];
        float4 g0 = *(float4*)&saT[k * TILE_N + ng * 8];
        float4 g1 = *(float4*)&saT[k * TILE_N + ng * 8 + 4];
        ulonglong2 b0 = *(ulonglong2*)&swT[k * D + dg * 8];
        ulonglong2 b1 = *(ulonglong2*)&swT[k * D + dg * 8 + 4];
        ulonglong2 c0 = *(ulonglong2*)&snT[k * D + dg * 8];
        ulonglong2 c1 = *(ulonglong2*)&snT[k * D + dg * 8 + 4];
        unsigned long long bv[4] = {b0.x, b0.y, b1.x, b1.y};
        unsigned long long cv[4] = {c0.x, c0.y, c1.x, c1.y};
        float av[8] = {a0.x, a0.y, a0.z, a0.w, a1.x, a1.y, a1.z, a1.w};
        float gv[8] = {g0.x, g0.y, g0.z, g0.w, g1.x, g1.y, g1.z, g1.w};
        #pragma unroll
        for (int i = 0; i < 8; i++) {
            unsigned long long ad = dup2(av[i]);
            unsigned long long gd = dup2(gv[i]);
            #pragma unroll
            for (int j = 0; j < 4; j++) {
                ffma2(acc[i][j], ad, bv[j]);
                ffma2(acc[i][j], gd, cv[j]);
            }
        }
    }

    #pragma unroll
    for (int i = 0; i < 8; i++) {
        int gn = nbase + ng * 8 + i;
        if (gn >= n_nodes) continue;
        const float* xr = x + (size_t)gn * D + dg * 8;
        float* orow = out + (size_t)gn * D + dg * 8;
        float4 x0 = *(const float4*)(xr);
        float4 x1 = *(const float4*)(xr + 4);
        float r0, r1, r2, r3, r4, r5, r6, r7;
        unpack2(acc[i][0], r0, r1);
        unpack2(acc[i][1], r2, r3);
        unpack2(acc[i][2], r4, r5);
        unpack2(acc[i][3], r6, r7);
        float4 o0 = make_float4(r0 + TAUF * x0.x, r1 + TAUF * x0.y,
                                r2 + TAUF * x0.z, r3 + TAUF * x0.w);
        float4 o1 = make_float4(r4 + TAUF * x1.x, r5 + TAUF * x1.y,
                                r6 + TAUF * x1.z, r7 + TAUF * x1.w);
        *(float4*)(orow)     = o0;
        *(float4*)(orow + 4) = o1;
    }
}

extern "C" void kernel_launch(void* const* d_in, const int* in_sizes, int n_in,
                              void* d_out, int out_size) {
    const float* x  = (const float*)d_in[0];
    const void*  ei = d_in[1];
    const float* w  = (const float*)d_in[2];
    const float* Ws = (const float*)d_in[3];
    const float* Wn = (const float*)d_in[4];

    int n_nodes = in_sizes[0] / D;
    int n_edges = in_sizes[1] / 2;

    float* out_main = (float*)d_out;
    float* out_ei = nullptr;
    float* out_wn = nullptr;
    long long need_full = (long long)n_nodes * D + 3LL * n_edges;
    bool full = ((long long)out_size >= need_full);
    if (full) {
        out_ei = out_main + (size_t)n_nodes * D;
        out_wn = out_ei + (size_t)2 * n_edges;
    }

    const int T = 256;
    int nblk = (n_nodes + T - 1) / T;
    int eblk = (n_edges + T - 1) / T;

    k_init<<<nblk, T>>>((const int*)ei, n_nodes);
    k_cvtdeg<<<eblk, T>>>(ei, w, out_ei, n_edges);
    k_kappa<<<eblk, T>>>(n_edges, n_nodes);
    k_whalf<<<eblk, T>>>(w, n_edges);

    int gw_blocks = ((long long)n_nodes * 32 + T - 1) / T;  // 12500 >= eblk
    k_gather<<<gw_blocks, T>>>(x, out_wn, n_edges, n_nodes);

    int smem_bytes = (D * TILE_N * 2 + D * D * 2) * (int)sizeof(float); // 96KB
    cudaFuncSetAttribute(k_gemm, cudaFuncAttributeMaxDynamicSharedMemorySize, smem_bytes);
    int gblocks = (n_nodes + TILE_N - 1) / TILE_N;
    k_gemm<<<gblocks, 128, smem_bytes>>>(x, Ws, Wn, out_main, n_nodes);
}

// round 14
// speedup vs baseline: 1.0426x; 1.0426x over previous
#include <cuda_runtime.h>
#include <cstdint>
#include <math.h>

#define MAXN 100000
#define MAXE 1600000
#define D 64
#define EPSF 1e-12f
#define SEPS 1e-6f
#define TAUF 0.5f

// ---- scratch (device globals: no allocation allowed) ----
__device__ __align__(8)  float2 g_deghist[MAXN];   // {weighted deg, edge count}
__device__ float    g_rho[MAXN];
__device__ int      g_start[MAXN];     // CSR row start
__device__ int      g_cursor[MAXN];    // fill cursor
__device__ int      g_row[MAXE];
__device__ int      g_col[MAXE];
__device__ float    g_kappa[MAXE];
__device__ __align__(16) float4 g_pay[MAXE];  // {bitcast col, wh, kappa, bitcast eid}
__device__ __align__(16) float g_agg[MAXN * D];
__device__ unsigned g_maxbits;
__device__ int      g_base;
__device__ int      g_is64;

__device__ __forceinline__ int get_idx(const void* ei, long long pos) {
    if (g_is64) return (int)((const long long*)ei)[pos];
    return ((const int*)ei)[pos];
}

// ---- 0: zero node scratch + dtype detect (block 0) ----
__global__ void k_init(const int* __restrict__ eib, int n_nodes) {
    if (blockIdx.x == 0) {
        __shared__ int any;
        if (threadIdx.x == 0) any = 0;
        __syncthreads();
        int acc = 0;
        for (int j = threadIdx.x; j < 2048; j += blockDim.x)
            acc |= eib[2 * j + 1];
        if (acc != 0) atomicOr(&any, 1);
        __syncthreads();
        if (threadIdx.x == 0) {
            g_is64 = (any == 0) ? 1 : 0;
            g_maxbits = 0u;
            g_base = 0;
        }
    }
    int i = blockIdx.x * blockDim.x + threadIdx.x;
    if (i < n_nodes)
        g_deghist[i] = make_float2(0.f, 0.f);
}

// ---- 1: convert + edge_index output + fused {deg,count} v2 reduction ----
__global__ void k_cvtdeg(const void* __restrict__ ei, const float* __restrict__ w,
                         float* __restrict__ out_ei, int n_edges) {
    int e = blockIdx.x * blockDim.x + threadIdx.x;
    if (e >= n_edges) return;
    int r = get_idx(ei, e);
    int c = get_idx(ei, (long long)n_edges + e);
    g_row[e] = r;
    g_col[e] = c;
    if (out_ei) {
        out_ei[e] = (float)r;
        out_ei[n_edges + e] = (float)c;
    }
    float* dst = (float*)&g_deghist[r];
    asm volatile("red.global.add.v2.f32 [%0], {%1,%2};"
                 :: "l"(dst), "f"(w[e]), "f"(1.0f) : "memory");
}

// ---- 2: kappa per edge (stored) + global max|kappa|; rider: CSR row starts ----
__global__ void k_kappa(int n_edges, int n_nodes) {
    __shared__ int sh[256];
    __shared__ int sbase;
    int t = threadIdx.x;

    if (blockIdx.x * 256u < (unsigned)n_nodes) {
        int n = blockIdx.x * 256 + t;
        int v = (n < n_nodes) ? (int)g_deghist[n].y : 0;
        sh[t] = v;
        __syncthreads();
        #pragma unroll
        for (int o = 1; o < 256; o <<= 1) {
            int u = (t >= o) ? sh[t - o] : 0;
            __syncthreads();
            sh[t] += u;
            __syncthreads();
        }
        int incl = sh[t];
        if (t == 255) sbase = atomicAdd(&g_base, incl);
        __syncthreads();
        if (n < n_nodes) {
            int s = sbase + incl - v;
            g_start[n] = s;
            g_cursor[n] = s;
        }
    }

    int e = blockIdx.x * blockDim.x + t;
    float m = 0.f;
    if (e < n_edges) {
        float idu = 2.f / fmaxf(g_deghist[g_row[e]].x, EPSF);
        float idv = 2.f / fmaxf(g_deghist[g_col[e]].x, EPSF);
        float kap = idu + idv - 2.f;
        g_kappa[e] = kap;
        m = fabsf(kap);
    }
    #pragma unroll
    for (int o = 16; o > 0; o >>= 1)
        m = fmaxf(m, __shfl_xor_sync(0xffffffffu, m, o));
    if ((t & 31) == 0)
        atomicMax(&g_maxbits, __float_as_uint(m));
}

// ---- 3: half-step + surgery + scatter self-contained 16B payload ----
__global__ void k_fill(const float* __restrict__ w, int n_edges) {
    int e = blockIdx.x * blockDim.x + threadIdx.x;
    if (e >= n_edges) return;
    float dt = 0.5f / (__uint_as_float(g_maxbits) + 1e-6f);
    float kap = g_kappa[e];
    float wh = fmaxf(w[e] * (1.f - 0.5f * dt * kap), 0.f);
    if (wh <= SEPS) wh = 0.f;
    int r = g_row[e];
    int pos = atomicAdd(&g_cursor[r], 1);
    g_pay[pos] = make_float4(__int_as_float(g_col[e]), wh, kap,
                             __int_as_float(e));
}

// ---- 4: single-pass gather: stats + accumulate + rho + out_wn ----
__global__ void k_gather(const float* __restrict__ x,
                         float* __restrict__ out_wn, int n_nodes) {
    int node = (blockIdx.x * blockDim.x + threadIdx.x) >> 5;
    if (node >= n_nodes) return;
    int lane = threadIdx.x & 31;
    int sub  = lane & 15;
    int half = lane >> 4;
    int s = g_start[node];
    int deg = (int)g_deghist[node].y;

    float rs = 0.f, cn = 0.f, ks = 0.f;
    float4 acc = make_float4(0.f, 0.f, 0.f, 0.f);
    #pragma unroll 2
    for (int j = half; j < deg; j += 2) {
        float4 pl = g_pay[s + j];          // {col, wh, kappa, eid}
        float wh = pl.y;
        rs += wh;                           // uniform across sub-lanes
        if (wh != 0.f) {
            cn += 1.f;
            ks += pl.z;
            int c = __float_as_int(pl.x);
            float4 v = ((const float4*)(x + (size_t)c * D))[sub];
            acc.x += wh * v.x; acc.y += wh * v.y;
            acc.z += wh * v.z; acc.w += wh * v.w;
        }
    }
    // merge the two halves; stats become identical across all lanes
    rs += __shfl_xor_sync(0xffffffffu, rs, 16);
    cn += __shfl_xor_sync(0xffffffffu, cn, 16);
    ks += __shfl_xor_sync(0xffffffffu, ks, 16);
    acc.x += __shfl_xor_sync(0xffffffffu, acc.x, 16);
    acc.y += __shfl_xor_sync(0xffffffffu, acc.y, 16);
    acc.z += __shfl_xor_sync(0xffffffffu, acc.z, 16);
    acc.w += __shfl_xor_sync(0xffffffffu, acc.w, 16);

    float irs = 1.f / fmaxf(rs, EPSF);
    if (lane == 0) {
        float mk = ks / fmaxf(cn, 1.f);
        g_rho[node] = 1.f / (1.f + expf(-mk));
    }
    if (half == 0) {
        acc.x *= irs; acc.y *= irs; acc.z *= irs; acc.w *= irs;
        *(float4*)(g_agg + (size_t)node * D + sub * 4) = acc;
    }

    // second mini-loop over L1-hot payload: write w_norm by original edge id
    if (out_wn) {
        for (int j = lane; j < deg; j += 32) {
            float4 pl = g_pay[s + j];
            out_wn[__float_as_int(pl.w)] = pl.y * irs;
        }
    }
}

// ---- FFMA2 helpers (packed f32x2, sm_103a) ----
__device__ __forceinline__ unsigned long long dup2(float v) {
    unsigned long long r;
    asm("mov.b64 %0, {%1, %1};" : "=l"(r) : "r"(__float_as_uint(v)));
    return r;
}
__device__ __forceinline__ void ffma2(unsigned long long& acc,
                                      unsigned long long a, unsigned long long b) {
    asm("fma.rn.f32x2 %0, %1, %2, %0;" : "+l"(acc) : "l"(a), "l"(b));
}
__device__ __forceinline__ void unpack2(unsigned long long v, float& lo, float& hi) {
    unsigned l, h;
    asm("mov.b64 {%0, %1}, %2;" : "=r"(l), "=r"(h) : "l"(v));
    lo = __uint_as_float(l); hi = __uint_as_float(h);
}

// ---- 5: fused dual GEMM (FFMA2): out = (rho*x)@Ws^T + agg@Wn^T + tau*x ----
#define TILE_N 128
__global__ __launch_bounds__(128, 2) void k_gemm(const float* __restrict__ x,
                                                 const float* __restrict__ Ws,
                                                 const float* __restrict__ Wn,
                                                 float* __restrict__ out,
                                                 int n_nodes) {
    extern __shared__ float smem[];
    float* sxT = smem;
    float* saT = sxT + D * TILE_N;
    float* swT = saT + D * TILE_N;
    float* snT = swT + D * D;

    int t = threadIdx.x;
    int nbase = blockIdx.x * TILE_N;

    for (int i = t; i < D * D; i += 128) {
        int k = i >> 6, d = i & 63;
        swT[k * D + d] = Ws[d * D + k];
        snT[k * D + d] = Wn[d * D + k];
    }
    for (int i = t; i < TILE_N * (D / 4); i += 128) {
        int n  = i & (TILE_N - 1);
        int k4 = i >> 7;
        int gn = nbase + n;
        float4 xv = make_float4(0.f, 0.f, 0.f, 0.f);
        float4 av = make_float4(0.f, 0.f, 0.f, 0.f);
        float rho = 0.f;
        if (gn < n_nodes) {
            xv  = *(const float4*)(x     + (size_t)gn * D + k4 * 4);
            av  = *(const float4*)(g_agg + (size_t)gn * D + k4 * 4);
            rho = g_rho[gn];
        }
        sxT[(k4 * 4 + 0) * TILE_N + n] = rho * xv.x;
        sxT[(k4 * 4 + 1) * TILE_N + n] = rho * xv.y;
        sxT[(k4 * 4 + 2) * TILE_N + n] = rho * xv.z;
        sxT[(k4 * 4 + 3) * TILE_N + n] = rho * xv.w;
        saT[(k4 * 4 + 0) * TILE_N + n] = av.x;
        saT[(k4 * 4 + 1) * TILE_N + n] = av.y;
        saT[(k4 * 4 + 2) * TILE_N + n] = av.z;
        saT[(k4 * 4 + 3) * TILE_N + n] = av.w;
    }
    __syncthreads();

    int ng = t >> 3;
    int dg = t & 7;

    unsigned long long acc[8][4];
    #pragma unroll
    for (int i = 0; i < 8; i++)
        #pragma unroll
        for (int j = 0; j < 4; j++) acc[i][j] = 0ull;

    #pragma unroll 2
    for (int k = 0; k < D; k++) {
        float4 a0 = *(float4*)&sxT[k * TILE_N + ng * 8];
        float4 a1 = *(float4*)&sxT[k * TILE_N + ng * 8 + 4];
        float4 g0 = *(float4*)&saT[k * TILE_N + ng * 8];
        float4 g1 = *(float4*)&saT[k * TILE_N + ng * 8 + 4];
        ulonglong2 b0 = *(ulonglong2*)&swT[k * D + dg * 8];
        ulonglong2 b1 = *(ulonglong2*)&swT[k * D + dg * 8 + 4];
        ulonglong2 c0 = *(ulonglong2*)&snT[k * D + dg * 8];
        ulonglong2 c1 = *(ulonglong2*)&snT[k * D + dg * 8 + 4];
        unsigned long long bv[4] = {b0.x, b0.y, b1.x, b1.y};
        unsigned long long cv[4] = {c0.x, c0.y, c1.x, c1.y};
        float av[8] = {a0.x, a0.y, a0.z, a0.w, a1.x, a1.y, a1.z, a1.w};
        float gv[8] = {g0.x, g0.y, g0.z, g0.w, g1.x, g1.y, g1.z, g1.w};
        #pragma unroll
        for (int i = 0; i < 8; i++) {
            unsigned long long ad = dup2(av[i]);
            unsigned long long gd = dup2(gv[i]);
            #pragma unroll
            for (int j = 0; j < 4; j++) {
                ffma2(acc[i][j], ad, bv[j]);
                ffma2(acc[i][j], gd, cv[j]);
            }
        }
    }

    #pragma unroll
    for (int i = 0; i < 8; i++) {
        int gn = nbase + ng * 8 + i;
        if (gn >= n_nodes) continue;
        const float* xr = x + (size_t)gn * D + dg * 8;
        float* orow = out + (size_t)gn * D + dg * 8;
        float4 x0 = *(const float4*)(xr);
        float4 x1 = *(const float4*)(xr + 4);
        float r0, r1, r2, r3, r4, r5, r6, r7;
        unpack2(acc[i][0], r0, r1);
        unpack2(acc[i][1], r2, r3);
        unpack2(acc[i][2], r4, r5);
        unpack2(acc[i][3], r6, r7);
        float4 o0 = make_float4(r0 + TAUF * x0.x, r1 + TAUF * x0.y,
                                r2 + TAUF * x0.z, r3 + TAUF * x0.w);
        float4 o1 = make_float4(r4 + TAUF * x1.x, r5 + TAUF * x1.y,
                                r6 + TAUF * x1.z, r7 + TAUF * x1.w);
        *(float4*)(orow)     = o0;
        *(float4*)(orow + 4) = o1;
    }
}

extern "C" void kernel_launch(void* const* d_in, const int* in_sizes, int n_in,
                              void* d_out, int out_size) {
    const float* x  = (const float*)d_in[0];
    const void*  ei = d_in[1];
    const float* w  = (const float*)d_in[2];
    const float* Ws = (const float*)d_in[3];
    const float* Wn = (const float*)d_in[4];

    int n_nodes = in_sizes[0] / D;
    int n_edges = in_sizes[1] / 2;

    float* out_main = (float*)d_out;
    float* out_ei = nullptr;
    float* out_wn = nullptr;
    long long need_full = (long long)n_nodes * D + 3LL * n_edges;
    bool full = ((long long)out_size >= need_full);
    if (full) {
        out_ei = out_main + (size_t)n_nodes * D;
        out_wn = out_ei + (size_t)2 * n_edges;
    }

    const int T = 256;
    int nblk = (n_nodes + T - 1) / T;
    int eblk = (n_edges + T - 1) / T;

    k_init<<<nblk, T>>>((const int*)ei, n_nodes);
    k_cvtdeg<<<eblk, T>>>(ei, w, out_ei, n_edges);
    k_kappa<<<eblk, T>>>(n_edges, n_nodes);
    k_fill<<<eblk, T>>>(w, n_edges);

    int gw_blocks = ((long long)n_nodes * 32 + T - 1) / T;
    k_gather<<<gw_blocks, T>>>(x, out_wn, n_nodes);

    int smem_bytes = (D * TILE_N * 2 + D * D * 2) * (int)sizeof(float); // 96KB
    cudaFuncSetAttribute(k_gemm, cudaFuncAttributeMaxDynamicSharedMemorySize, smem_bytes);
    int gblocks = (n_nodes + TILE_N - 1) / TILE_N;
    k_gemm<<<gblocks, 128, smem_bytes>>>(x, Ws, Wn, out_main, n_nodes);
}

// round 15
// speedup vs baseline: 1.1838x; 1.1355x over previous
#include <cuda_runtime.h>
#include <cstdint>
#include <math.h>

#define MAXN 100000
#define MAXE 1600000
#define D 64
#define EPSF 1e-12f
#define SEPS 1e-6f
#define TAUF 0.5f

#define EBLOCKS 592          // 4 blocks/SM x 148 SMs (<= capacity on 152-SM GB300 too)
#define ETHREADS 256
#define NT (EBLOCKS * ETHREADS)   // 151552 persistent threads
#define MAXK 12                   // ceil(1.6M / NT) = 11

// ---- scratch (device globals: no allocation allowed) ----
__device__ __align__(8)  float2 g_deghist[MAXN];   // {weighted deg, edge count}
__device__ float    g_rho[MAXN];
__device__ int      g_start[MAXN];     // CSR row start
__device__ int      g_cursor[MAXN];    // fill cursor
__device__ __align__(16) float4 g_pay[MAXE];  // {bitcast col, wh, kappa, bitcast eid}
__device__ __align__(16) float g_agg[MAXN * D];
__device__ unsigned g_maxbits;
__device__ int      g_base;
__device__ int      g_is64;
__device__ int      g_bar1, g_bar2;

__device__ __forceinline__ int get_idx(const void* ei, long long pos) {
    if (g_is64) return (int)((const long long*)ei)[pos];
    return ((const int*)ei)[pos];
}

// ---- 0: zero node scratch + barrier counters + dtype detect (block 0) ----
__global__ void k_init(const int* __restrict__ eib, int n_nodes) {
    if (blockIdx.x == 0) {
        __shared__ int any;
        if (threadIdx.x == 0) any = 0;
        __syncthreads();
        int acc = 0;
        for (int j = threadIdx.x; j < 2048; j += blockDim.x)
            acc |= eib[2 * j + 1];
        if (acc != 0) atomicOr(&any, 1);
        __syncthreads();
        if (threadIdx.x == 0) {
            g_is64 = (any == 0) ? 1 : 0;
            g_maxbits = 0u;
            g_base = 0;
            g_bar1 = 0;
            g_bar2 = 0;
        }
    }
    int i = blockIdx.x * blockDim.x + threadIdx.x;
    if (i < n_nodes)
        g_deghist[i] = make_float2(0.f, 0.f);
}

// software grid barrier: all EBLOCKS blocks are co-resident by construction
__device__ __forceinline__ void grid_barrier(int* bar) {
    __syncthreads();
    if (threadIdx.x == 0) {
        __threadfence();
        atomicAdd(bar, 1);
        while (atomicAdd(bar, 0) < EBLOCKS) { }
    }
    __syncthreads();
}

// ---- 1: persistent fused edge pipeline ----
// Phase A: convert + out_ei + {deg,count} reduction   (row/col kept in regs)
// Phase B: kappa (regs) + max|kappa| + CSR-start scan rider
// Phase C: half-step + surgery + scatter payload
__global__ void __launch_bounds__(ETHREADS, 4)
k_edge(const void* __restrict__ ei, const float* __restrict__ w,
       float* __restrict__ out_ei, int n_edges, int n_nodes) {
    int gtid = blockIdx.x * ETHREADS + threadIdx.x;

    int er[MAXK], ec[MAXK];
    float kap[MAXK];

    // ---- phase A ----
    #pragma unroll
    for (int k = 0; k < MAXK; k++) {
        int e = gtid + k * NT;
        er[k] = -1;
        if (e < n_edges) {
            int r = get_idx(ei, e);
            int c = get_idx(ei, (long long)n_edges + e);
            er[k] = r; ec[k] = c;
            if (out_ei) {
                out_ei[e] = (float)r;
                out_ei[n_edges + e] = (float)c;
            }
            float* dst = (float*)&g_deghist[r];
            asm volatile("red.global.add.v2.f32 [%0], {%1,%2};"
                         :: "l"(dst), "f"(w[e]), "f"(1.0f) : "memory");
        }
    }

    grid_barrier(&g_bar1);

    // ---- phase B: kappa + max reduction ----
    float m = 0.f;
    #pragma unroll
    for (int k = 0; k < MAXK; k++) {
        if (er[k] >= 0) {
            float idu = 2.f / fmaxf(g_deghist[er[k]].x, EPSF);
            float idv = 2.f / fmaxf(g_deghist[ec[k]].x, EPSF);
            kap[k] = idu + idv - 2.f;
            m = fmaxf(m, fabsf(kap[k]));
        }
    }
    #pragma unroll
    for (int o = 16; o > 0; o >>= 1)
        m = fmaxf(m, __shfl_xor_sync(0xffffffffu, m, o));
    if ((threadIdx.x & 31) == 0)
        atomicMax(&g_maxbits, __float_as_uint(m));

    // rider: CSR row starts (blocks over node chunks)
    {
        __shared__ int sh[ETHREADS];
        __shared__ int sbase;
        int t = threadIdx.x;
        if (blockIdx.x * ETHREADS < (unsigned)n_nodes) {
            int n = blockIdx.x * ETHREADS + t;
            int v = (n < n_nodes) ? (int)g_deghist[n].y : 0;
            sh[t] = v;
            __syncthreads();
            #pragma unroll
            for (int o = 1; o < ETHREADS; o <<= 1) {
                int u = (t >= o) ? sh[t - o] : 0;
                __syncthreads();
                sh[t] += u;
                __syncthreads();
            }
            int incl = sh[t];
            if (t == ETHREADS - 1) sbase = atomicAdd(&g_base, incl);
            __syncthreads();
            if (n < n_nodes) {
                int s = sbase + incl - v;
                g_start[n] = s;
                g_cursor[n] = s;
            }
        }
    }

    grid_barrier(&g_bar2);

    // ---- phase C: whalf + surgery + payload scatter ----
    float dt = 0.5f / (__uint_as_float(g_maxbits) + 1e-6f);
    #pragma unroll
    for (int k = 0; k < MAXK; k++) {
        int e = gtid + k * NT;
        if (er[k] >= 0) {
            float wh = fmaxf(w[e] * (1.f - 0.5f * dt * kap[k]), 0.f);
            if (wh <= SEPS) wh = 0.f;
            int pos = atomicAdd(&g_cursor[er[k]], 1);
            g_pay[pos] = make_float4(__int_as_float(ec[k]), wh, kap[k],
                                     __int_as_float(e));
        }
    }
}

// ---- 2: single-pass gather: stats + accumulate + rho + out_wn ----
__global__ void k_gather(const float* __restrict__ x,
                         float* __restrict__ out_wn, int n_nodes) {
    int node = (blockIdx.x * blockDim.x + threadIdx.x) >> 5;
    if (node >= n_nodes) return;
    int lane = threadIdx.x & 31;
    int sub  = lane & 15;
    int half = lane >> 4;
    int s = g_start[node];
    int deg = (int)g_deghist[node].y;

    float rs = 0.f, cn = 0.f, ks = 0.f;
    float4 acc = make_float4(0.f, 0.f, 0.f, 0.f);
    #pragma unroll 2
    for (int j = half; j < deg; j += 2) {
        float4 pl = g_pay[s + j];          // {col, wh, kappa, eid}
        float wh = pl.y;
        rs += wh;
        if (wh != 0.f) {
            cn += 1.f;
            ks += pl.z;
            int c = __float_as_int(pl.x);
            float4 v = ((const float4*)(x + (size_t)c * D))[sub];
            acc.x += wh * v.x; acc.y += wh * v.y;
            acc.z += wh * v.z; acc.w += wh * v.w;
        }
    }
    rs += __shfl_xor_sync(0xffffffffu, rs, 16);
    cn += __shfl_xor_sync(0xffffffffu, cn, 16);
    ks += __shfl_xor_sync(0xffffffffu, ks, 16);
    acc.x += __shfl_xor_sync(0xffffffffu, acc.x, 16);
    acc.y += __shfl_xor_sync(0xffffffffu, acc.y, 16);
    acc.z += __shfl_xor_sync(0xffffffffu, acc.z, 16);
    acc.w += __shfl_xor_sync(0xffffffffu, acc.w, 16);

    float irs = 1.f / fmaxf(rs, EPSF);
    if (lane == 0) {
        float mk = ks / fmaxf(cn, 1.f);
        g_rho[node] = 1.f / (1.f + expf(-mk));
    }
    if (half == 0) {
        acc.x *= irs; acc.y *= irs; acc.z *= irs; acc.w *= irs;
        *(float4*)(g_agg + (size_t)node * D + sub * 4) = acc;
    }

    if (out_wn) {
        for (int j = lane; j < deg; j += 32) {
            float4 pl = g_pay[s + j];
            out_wn[__float_as_int(pl.w)] = pl.y * irs;
        }
    }
}

// ---- FFMA2 helpers (packed f32x2, sm_103a) ----
__device__ __forceinline__ unsigned long long dup2(float v) {
    unsigned long long r;
    asm("mov.b64 %0, {%1, %1};" : "=l"(r) : "r"(__float_as_uint(v)));
    return r;
}
__device__ __forceinline__ void ffma2(unsigned long long& acc,
                                      unsigned long long a, unsigned long long b) {
    asm("fma.rn.f32x2 %0, %1, %2, %0;" : "+l"(acc) : "l"(a), "l"(b));
}
__device__ __forceinline__ void unpack2(unsigned long long v, float& lo, float& hi) {
    unsigned l, h;
    asm("mov.b64 {%0, %1}, %2;" : "=r"(l), "=r"(h) : "l"(v));
    lo = __uint_as_float(l); hi = __uint_as_float(h);
}

// ---- 3: fused dual GEMM (FFMA2): out = (rho*x)@Ws^T + agg@Wn^T + tau*x ----
#define TILE_N 128
__global__ __launch_bounds__(128, 2) void k_gemm(const float* __restrict__ x,
                                                 const float* __restrict__ Ws,
                                                 const float* __restrict__ Wn,
                                                 float* __restrict__ out,
                                                 int n_nodes) {
    extern __shared__ float smem[];
    float* sxT = smem;
    float* saT = sxT + D * TILE_N;
    float* swT = saT + D * TILE_N;
    float* snT = swT + D * D;

    int t = threadIdx.x;
    int nbase = blockIdx.x * TILE_N;

    for (int i = t; i < D * D; i += 128) {
        int k = i >> 6, d = i & 63;
        swT[k * D + d] = Ws[d * D + k];
        snT[k * D + d] = Wn[d * D + k];
    }
    for (int i = t; i < TILE_N * (D / 4); i += 128) {
        int n  = i & (TILE_N - 1);
        int k4 = i >> 7;
        int gn = nbase + n;
        float4 xv = make_float4(0.f, 0.f, 0.f, 0.f);
        float4 av = make_float4(0.f, 0.f, 0.f, 0.f);
        float rho = 0.f;
        if (gn < n_nodes) {
            xv  = *(const float4*)(x     + (size_t)gn * D + k4 * 4);
            av  = *(const float4*)(g_agg + (size_t)gn * D + k4 * 4);
            rho = g_rho[gn];
        }
        sxT[(k4 * 4 + 0) * TILE_N + n] = rho * xv.x;
        sxT[(k4 * 4 + 1) * TILE_N + n] = rho * xv.y;
        sxT[(k4 * 4 + 2) * TILE_N + n] = rho * xv.z;
        sxT[(k4 * 4 + 3) * TILE_N + n] = rho * xv.w;
        saT[(k4 * 4 + 0) * TILE_N + n] = av.x;
        saT[(k4 * 4 + 1) * TILE_N + n] = av.y;
        saT[(k4 * 4 + 2) * TILE_N + n] = av.z;
        saT[(k4 * 4 + 3) * TILE_N + n] = av.w;
    }
    __syncthreads();

    int ng = t >> 3;
    int dg = t & 7;

    unsigned long long acc[8][4];
    #pragma unroll
    for (int i = 0; i < 8; i++)
        #pragma unroll
        for (int j = 0; j < 4; j++) acc[i][j] = 0ull;

    #pragma unroll 2
    for (int k = 0; k < D; k++) {
        float4 a0 = *(float4*)&sxT[k * TILE_N + ng * 8];
        float4 a1 = *(float4*)&sxT[k * TILE_N + ng * 8 + 4];
        float4 g0 = *(float4*)&saT[k * TILE_N + ng * 8];
        float4 g1 = *(float4*)&saT[k * TILE_N + ng * 8 + 4];
        ulonglong2 b0 = *(ulonglong2*)&swT[k * D + dg * 8];
        ulonglong2 b1 = *(ulonglong2*)&swT[k * D + dg * 8 + 4];
        ulonglong2 c0 = *(ulonglong2*)&snT[k * D + dg * 8];
        ulonglong2 c1 = *(ulonglong2*)&snT[k * D + dg * 8 + 4];
        unsigned long long bv[4] = {b0.x, b0.y, b1.x, b1.y};
        unsigned long long cv[4] = {c0.x, c0.y, c1.x, c1.y};
        float av[8] = {a0.x, a0.y, a0.z, a0.w, a1.x, a1.y, a1.z, a1.w};
        float gv[8] = {g0.x, g0.y, g0.z, g0.w, g1.x, g1.y, g1.z, g1.w};
        #pragma unroll
        for (int i = 0; i < 8; i++) {
            unsigned long long ad = dup2(av[i]);
            unsigned long long gd = dup2(gv[i]);
            #pragma unroll
            for (int j = 0; j < 4; j++) {
                ffma2(acc[i][j], ad, bv[j]);
                ffma2(acc[i][j], gd, cv[j]);
            }
        }
    }

    #pragma unroll
    for (int i = 0; i < 8; i++) {
        int gn = nbase + ng * 8 + i;
        if (gn >= n_nodes) continue;
        const float* xr = x + (size_t)gn * D + dg * 8;
        float* orow = out + (size_t)gn * D + dg * 8;
        float4 x0 = *(const float4*)(xr);
        float4 x1 = *(const float4*)(xr + 4);
        float r0, r1, r2, r3, r4, r5, r6, r7;
        unpack2(acc[i][0], r0, r1);
        unpack2(acc[i][1], r2, r3);
        unpack2(acc[i][2], r4, r5);
        unpack2(acc[i][3], r6, r7);
        float4 o0 = make_float4(r0 + TAUF * x0.x, r1 + TAUF * x0.y,
                                r2 + TAUF * x0.z, r3 + TAUF * x0.w);
        float4 o1 = make_float4(r4 + TAUF * x1.x, r5 + TAUF * x1.y,
                                r6 + TAUF * x1.z, r7 + TAUF * x1.w);
        *(float4*)(orow)     = o0;
        *(float4*)(orow + 4) = o1;
    }
}

extern "C" void kernel_launch(void* const* d_in, const int* in_sizes, int n_in,
                              void* d_out, int out_size) {
    const float* x  = (const float*)d_in[0];
    const void*  ei = d_in[1];
    const float* w  = (const float*)d_in[2];
    const float* Ws = (const float*)d_in[3];
    const float* Wn = (const float*)d_in[4];

    int n_nodes = in_sizes[0] / D;
    int n_edges = in_sizes[1] / 2;

    float* out_main = (float*)d_out;
    float* out_ei = nullptr;
    float* out_wn = nullptr;
    long long need_full = (long long)n_nodes * D + 3LL * n_edges;
    bool full = ((long long)out_size >= need_full);
    if (full) {
        out_ei = out_main + (size_t)n_nodes * D;
        out_wn = out_ei + (size_t)2 * n_edges;
    }

    const int T = 256;
    int nblk = (n_nodes + T - 1) / T;

    k_init<<<nblk, T>>>((const int*)ei, n_nodes);
    k_edge<<<EBLOCKS, ETHREADS>>>(ei, w, out_ei, n_edges, n_nodes);

    int gw_blocks = ((long long)n_nodes * 32 + T - 1) / T;
    k_gather<<<gw_blocks, T>>>(x, out_wn, n_nodes);

    int smem_bytes = (D * TILE_N * 2 + D * D * 2) * (int)sizeof(float); // 96KB
    cudaFuncSetAttribute(k_gemm, cudaFuncAttributeMaxDynamicSharedMemorySize, smem_bytes);
    int gblocks = (n_nodes + TILE_N - 1) / TILE_N;
    k_gemm<<<gblocks, 128, smem_bytes>>>(x, Ws, Wn, out_main, n_nodes);
}